// round 1
// baseline (speedup 1.0000x reference)
#include <cuda_runtime.h>
#include <cuda_bf16.h>
#include <cstdint>

// Problem constants
#define NB   32
#define NN   512
#define FIN  64
#define NH   4
#define HID  64
#define HF   256   // NH*HID
#define FOUT 64

// Scratch (static device arrays; no allocation)
__device__ float g_H1[NB * NN * HF];       // layer-1 projections h = x@W1   (16 MB)
__device__ float g_E1s[NB * NN * NH];
__device__ float g_E1d[NB * NN * NH];
__device__ float g_H2[NB * NN * FOUT];     // layer-2 projections h2 = elu(agg1)@W2 (4 MB)
__device__ float g_E2s[NB * NN];
__device__ float g_E2d[NB * NN];

// ---------------------------------------------------------------------------
// Kernel A: H1 = x @ W1, plus e1_src[n,h] = <h[n,h,:], a1_src[h,:]>, e1_dst.
// Grid (32, 8): batch, 64-row tile. 256 threads; thread t owns column c = t.
// W1 column hoisted to registers (64 regs), x tile staged in smem.
// ---------------------------------------------------------------------------
__global__ void __launch_bounds__(256) kA(const float* __restrict__ x,
                                          const float* __restrict__ W1,
                                          const float* __restrict__ a1s,
                                          const float* __restrict__ a1d) {
    __shared__ float xs[64 * FIN];
    __shared__ float rs[8], rd[8];
    const int b = blockIdx.x, row0 = blockIdx.y * 64;
    const int t = threadIdx.x, lane = t & 31, warp = t >> 5;

    const float* xp = x + ((size_t)(b * NN + row0)) * FIN;
    for (int i = t; i < 64 * FIN; i += 256) xs[i] = xp[i];

    float w1r[64];
#pragma unroll
    for (int k = 0; k < 64; k++) w1r[k] = W1[k * HF + t];
    const float asv = a1s[t], adv = a1d[t];
    __syncthreads();

    for (int r = 0; r < 64; r++) {
        float acc = 0.f;
#pragma unroll
        for (int k = 0; k < 64; k++) acc += xs[r * 64 + k] * w1r[k];
        g_H1[((size_t)(b * NN + row0 + r)) * HF + t] = acc;

        float ps = acc * asv, pd = acc * adv;
#pragma unroll
        for (int off = 16; off; off >>= 1) {
            ps += __shfl_down_sync(0xffffffffu, ps, off);
            pd += __shfl_down_sync(0xffffffffu, pd, off);
        }
        if (lane == 0) { rs[warp] = ps; rd[warp] = pd; }
        __syncthreads();
        if (t < NH) {
            int idx = (b * NN + row0 + r) * NH + t;
            g_E1s[idx] = rs[2 * t] + rs[2 * t + 1];
            g_E1d[idx] = rd[2 * t] + rd[2 * t + 1];
        }
        __syncthreads();
    }
}

// ---------------------------------------------------------------------------
// Kernel B: layer-1 attention aggregation (fused unnormalized-sum + Z), then
// +b1, ELU, proj2 (@W2), and e2_src/e2_dst. Grid (32, 16): batch, 32-dst tile.
// 256 threads; in aggregation thread t owns column c = t for all 32 dst rows.
// ---------------------------------------------------------------------------
__global__ void __launch_bounds__(256) kB(const int*   __restrict__ adj,
                                          const float* __restrict__ b1,
                                          const float* __restrict__ W2,
                                          const float* __restrict__ a2s,
                                          const float* __restrict__ a2d) {
    // Phase-1 layout inside big[10240] (40 KB):
    //   es   [2048]  @0      e1_src[s][h] for all 512 s
    //   ws   [4096]  @2048   exp-weight block: [sl(32)][h(4)][d(32)]
    //   maskw[512]u  @6144   bit d of word s: edge s->(d0+d) | selfloop
    //   ed   [128]   @6656   e1_dst[d][h] for the tile
    //   zp   [256]   @6784   Z partials
    // Phase-2 overlays (after all phase-1 reads complete):
    //   tile [8192]  @0      elu(agg)+b1, [d(32)][c(256)]
    //   h2s  [2048]  @8192   h2 tile [d(32)][o(64)]
    __shared__ __align__(16) float big[10240];
    __shared__ float Zs[128];
    float*    es    = big;
    float*    ws    = big + 2048;
    unsigned* maskw = (unsigned*)(big + 6144);
    float*    ed    = big + 6656;
    float*    zp    = big + 6784;
    float*    tile  = big;
    float*    h2s   = big + 8192;

    const int b = blockIdx.x, d0 = blockIdx.y * 32;
    const int t = threadIdx.x, lane = t & 31, warp = t >> 5;
    const int h = t >> 6;   // head of this thread's column

    for (int i = t; i < NN * NH; i += 256) es[i] = g_E1s[b * NN * NH + i];
    if (t < 128) ed[t] = g_E1d[(b * NN + d0) * NH + t];

    const int* ap = adj + (size_t)b * NN * NN + d0;
    for (int s = warp; s < NN; s += 8) {
        int a = ap[s * NN + lane];
        unsigned mw = __ballot_sync(0xffffffffu, (a != 0) || (s == d0 + lane));
        if (lane == 0) maskw[s] = mw;
    }
    __syncthreads();

    float acc[32];
#pragma unroll
    for (int i = 0; i < 32; i++) acc[i] = 0.f;
    float zpart = 0.f;

    // fill-mapping: thread t -> fixed (head fhh, dst fdd), covers 16 sl values
    const int   fhh  = (t & 127) >> 5, fdd = t & 31;
    const float fedv = ed[fdd * NH + fhh];

    const float* H1b = g_H1 + ((size_t)(b * NN)) * HF + t;

    for (int s0 = 0; s0 < NN; s0 += 32) {
        // cooperative weight block: w = mask ? exp(leaky(e_dst+e_src)) : 0
#pragma unroll
        for (int i = 0; i < 16; i++) {
            int sl = (t >> 7) + 2 * i;
            int s  = s0 + sl;
            float sc = fedv + es[s * NH + fhh];
            sc = sc >= 0.f ? sc : 0.2f * sc;
            float wv = ((maskw[s] >> fdd) & 1u) ? expf(sc) : 0.f;
            ws[(sl * NH + fhh) * 32 + fdd] = wv;
            zpart += wv;
        }
        __syncthreads();
        // aggregation: acc[d] += w[d,s,h] * H1[s,c]
#pragma unroll 4
        for (int sl = 0; sl < 32; sl++) {
            float hv = H1b[(size_t)(s0 + sl) * HF];
            const float4* wp = (const float4*)(ws + (sl * NH + h) * 32);
#pragma unroll
            for (int j = 0; j < 8; j++) {
                float4 w4 = wp[j];
                acc[4 * j + 0] += w4.x * hv;
                acc[4 * j + 1] += w4.y * hv;
                acc[4 * j + 2] += w4.z * hv;
                acc[4 * j + 3] += w4.w * hv;
            }
        }
        __syncthreads();
    }

    // reduce Z[d][h]: two threads (t, t+128) share each (fhh, fdd)
    zp[t] = zpart;
    __syncthreads();
    if (t < 128) Zs[(t & 31) * NH + (t >> 5)] = zp[t] + zp[t + 128];
    __syncthreads();

    // normalize + b1 + ELU -> tile (overwrites phase-1 smem; Zs lives outside)
    const float bv = b1[t];
#pragma unroll 8
    for (int d = 0; d < 32; d++) {
        float o = acc[d] / Zs[d * NH + h] + bv;
        tile[d * HF + t] = o > 0.f ? o : expm1f(o);
    }
    __syncthreads();

    // proj2: h2[d][o] = tile[d][:] @ W2[:, o]
    const int o = t & 63, grp = t >> 6;
    float acc2[8];
#pragma unroll
    for (int i = 0; i < 8; i++) acc2[i] = 0.f;
    for (int c = 0; c < HF; c++) {
        float wv = W2[c * FOUT + o];
#pragma unroll
        for (int i = 0; i < 8; i++)
            acc2[i] += tile[(grp * 8 + i) * HF + c] * wv;
    }
#pragma unroll
    for (int i = 0; i < 8; i++) {
        int d = grp * 8 + i;
        g_H2[((size_t)(b * NN + d0 + d)) * FOUT + o] = acc2[i];
        h2s[d * FOUT + o] = acc2[i];
    }
    __syncthreads();

    // e2_src/e2_dst for the tile
    if (t < 32) {
        float ssum = 0.f, dsum = 0.f;
        for (int o2 = 0; o2 < FOUT; o2++) {
            float v = h2s[t * FOUT + o2];
            ssum += v * a2s[o2];
            dsum += v * a2d[o2];
        }
        g_E2s[b * NN + d0 + t] = ssum;
        g_E2d[b * NN + d0 + t] = dsum;
    }
}

// ---------------------------------------------------------------------------
// Kernel C: layer-2 attention aggregation + b2 -> out. Grid (32, 16).
// 256 threads: thread t owns (o = t&63), dst rows grp*8 .. grp*8+7.
// ---------------------------------------------------------------------------
__global__ void __launch_bounds__(256) kC(const int*   __restrict__ adj,
                                          const float* __restrict__ b2,
                                          float*       __restrict__ out) {
    __shared__ float es2[NN];
    __shared__ float ed2[32];
    __shared__ unsigned maskw[NN];
    __shared__ __align__(16) float ws2[64 * 32];
    __shared__ float zp[256];
    __shared__ float Z2[32];

    const int b = blockIdx.x, d0 = blockIdx.y * 32;
    const int t = threadIdx.x, lane = t & 31, warp = t >> 5;

    for (int i = t; i < NN; i += 256) es2[i] = g_E2s[b * NN + i];
    if (t < 32) ed2[t] = g_E2d[b * NN + d0 + t];

    const int* ap = adj + (size_t)b * NN * NN + d0;
    for (int s = warp; s < NN; s += 8) {
        int a = ap[s * NN + lane];
        unsigned mw = __ballot_sync(0xffffffffu, (a != 0) || (s == d0 + lane));
        if (lane == 0) maskw[s] = mw;
    }
    __syncthreads();

    float acc[8];
#pragma unroll
    for (int i = 0; i < 8; i++) acc[i] = 0.f;
    float zpart = 0.f;

    const int   fdd  = t & 31, fslb = t >> 5;
    const float fedv = ed2[fdd];
    const int   o = t & 63, grp = t >> 6;
    const float* H2b = g_H2 + (size_t)b * NN * FOUT + o;

    for (int s0 = 0; s0 < NN; s0 += 64) {
#pragma unroll
        for (int i = 0; i < 8; i++) {
            int sl = fslb + 8 * i;
            int s  = s0 + sl;
            float sc = fedv + es2[s];
            sc = sc >= 0.f ? sc : 0.2f * sc;
            float wv = ((maskw[s] >> fdd) & 1u) ? expf(sc) : 0.f;
            ws2[sl * 32 + fdd] = wv;
            zpart += wv;
        }
        __syncthreads();
#pragma unroll 4
        for (int sl = 0; sl < 64; sl++) {
            float hv = H2b[(size_t)(s0 + sl) * FOUT];
            const float4* wp = (const float4*)(ws2 + sl * 32 + grp * 8);
            float4 w0 = wp[0], w1 = wp[1];
            acc[0] += w0.x * hv; acc[1] += w0.y * hv;
            acc[2] += w0.z * hv; acc[3] += w0.w * hv;
            acc[4] += w1.x * hv; acc[5] += w1.y * hv;
            acc[6] += w1.z * hv; acc[7] += w1.w * hv;
        }
        __syncthreads();
    }

    zp[t] = zpart;
    __syncthreads();
    if (t < 32) {
        float z = 0.f;
#pragma unroll
        for (int j = 0; j < 8; j++) z += zp[t + 32 * j];
        Z2[t] = z;
    }
    __syncthreads();

    const float bv = b2[o];
#pragma unroll
    for (int i = 0; i < 8; i++) {
        int d = grp * 8 + i;
        out[((size_t)(b * NN + d0 + d)) * FOUT + o] = acc[i] / Z2[d] + bv;
    }
}

// ---------------------------------------------------------------------------
extern "C" void kernel_launch(void* const* d_in, const int* in_sizes, int n_in,
                              void* d_out, int out_size) {
    const float* x   = (const float*)d_in[0];
    const int*   adj = (const int*)  d_in[1];
    const float* W1  = (const float*)d_in[2];
    const float* a1s = (const float*)d_in[3];
    const float* a1d = (const float*)d_in[4];
    const float* b1  = (const float*)d_in[5];
    const float* W2  = (const float*)d_in[6];
    const float* a2s = (const float*)d_in[7];
    const float* a2d = (const float*)d_in[8];
    const float* b2  = (const float*)d_in[9];
    float* out = (float*)d_out;

    kA<<<dim3(NB, 8),  256>>>(x, W1, a1s, a1d);
    kB<<<dim3(NB, 16), 256>>>(adj, b1, W2, a2s, a2d);
    kC<<<dim3(NB, 16), 256>>>(adj, b2, out);
}

// round 2
// speedup vs baseline: 1.5053x; 1.5053x over previous
#include <cuda_runtime.h>
#include <cuda_bf16.h>
#include <cstdint>

// Problem constants
#define NB   32
#define NN   512
#define FIN  64
#define NH   4
#define HID  64
#define HF   256   // NH*HID
#define FOUT 64

typedef unsigned long long u64;

// Scratch (static device arrays; no allocation)
__device__ float g_H1[NB * NN * HF];       // layer-1 projections h = x@W1   (16 MB)
__device__ float g_E1s[NB * NN * NH];
__device__ float g_E1d[NB * NN * NH];
__device__ float g_H2[NB * NN * FOUT];     // layer-2 projections (4 MB)
__device__ float g_E2s[NB * NN];
__device__ float g_E2d[NB * NN];

// ---- packed f32x2 helpers ----
__device__ __forceinline__ void ffma2(u64& d, u64 a, u64 b) {
    asm("fma.rn.f32x2 %0, %1, %2, %0;" : "+l"(d) : "l"(a), "l"(b));
}
__device__ __forceinline__ u64 pack2(float x, float y) {
    u64 r; asm("mov.b64 %0, {%1, %2};" : "=l"(r) : "f"(x), "f"(y)); return r;
}
__device__ __forceinline__ float2 unpack2(u64 v) {
    float2 r; asm("mov.b64 {%0, %1}, %2;" : "=f"(r.x), "=f"(r.y) : "l"(v)); return r;
}

// ---------------------------------------------------------------------------
// Kernel A: H1 = x @ W1 plus e1_src/e1_dst. Grid (32, 16): batch, 32-row tile.
// 256 threads. Phase 1: thread t owns output column t, packed-FMA dot.
// Phase 2: one (row, head, vec) dot per thread from the smem H-tile.
// ---------------------------------------------------------------------------
#define HS_STRIDE 264   // padded row stride for hs (breaks bank conflicts)

__global__ void __launch_bounds__(256) kA(const float* __restrict__ x,
                                          const float* __restrict__ W1,
                                          const float* __restrict__ a1s,
                                          const float* __restrict__ a1d) {
    __shared__ __align__(16) float xs[32 * FIN];        // 8 KB
    __shared__ __align__(16) float hs[32 * HS_STRIDE];  // 33 KB
    __shared__ __align__(16) float av[2 * HF];          // a1s | a1d (2 KB)

    const int b = blockIdx.x, row0 = blockIdx.y * 32;
    const int t = threadIdx.x;

    const float* xp = x + ((size_t)(b * NN + row0)) * FIN;
    for (int i = t; i < 32 * FIN; i += 256) xs[i] = xp[i];
    { // av: heads are 64 wide; a1s/a1d are [H][HID] contiguous = 256 floats
        av[t]      = a1s[t];
        av[t + HF] = a1d[t];
    }

    // W1 column t, packed over k
    u64 w1p[32];
#pragma unroll
    for (int kk = 0; kk < 32; kk++)
        w1p[kk] = pack2(W1[(2 * kk) * HF + t], W1[(2 * kk + 1) * HF + t]);
    __syncthreads();

    float* H1p = g_H1 + ((size_t)(b * NN + row0)) * HF + t;
    for (int r = 0; r < 32; r++) {
        const ulonglong2* xr = (const ulonglong2*)(xs + r * FIN);
        u64 aA = pack2(0.f, 0.f), aB = pack2(0.f, 0.f);
#pragma unroll
        for (int q = 0; q < 16; q++) {
            ulonglong2 xv = xr[q];
            ffma2(aA, xv.x, w1p[2 * q]);
            ffma2(aB, xv.y, w1p[2 * q + 1]);
        }
        float2 fa = unpack2(aA), fb = unpack2(aB);
        float acc = (fa.x + fa.y) + (fb.x + fb.y);
        hs[r * HS_STRIDE + t] = acc;
        H1p[(size_t)r * HF] = acc;
    }
    __syncthreads();

    // Phase 2: thread t -> row = t>>3, h = (t>>1)&3, vec = t&1
    {
        const int row = t >> 3, h = (t >> 1) & 3, vec = t & 1;
        const float4* hp = (const float4*)(hs + row * HS_STRIDE + h * HID);
        const float4* ap = (const float4*)(av + vec * HF + h * HID);
        float s = 0.f;
#pragma unroll
        for (int j = 0; j < 16; j++) {
            float4 hv = hp[j], aw = ap[j];
            s += hv.x * aw.x + hv.y * aw.y + hv.z * aw.z + hv.w * aw.w;
        }
        int idx = (b * NN + row0 + row) * NH + h;
        if (vec == 0) g_E1s[idx] = s; else g_E1d[idx] = s;
    }
}

// ---------------------------------------------------------------------------
// Kernel B: layer-1 attention aggregation (fused unnormalized-sum + Z), then
// +b1, ELU, proj2 (@W2), and e2_src/e2_dst. Grid (32, 16): batch, 32-dst tile.
// ---------------------------------------------------------------------------
#define H2S_STRIDE 72

__global__ void __launch_bounds__(256) kB(const int*   __restrict__ adj,
                                          const float* __restrict__ b1,
                                          const float* __restrict__ W2,
                                          const float* __restrict__ a2s,
                                          const float* __restrict__ a2d) {
    // Phase-1 layout inside big[10752] (42 KB):
    //   es   [2048]  @0      e1_src[s][h]
    //   ws   [4096]  @2048   weight block [sl(32)][h(4)][d(32)]
    //   maskw[512]u  @6144
    //   ed   [128]   @6656
    //   zp   [256]   @6784
    // Phase-2 overlays:
    //   tile [8192]  @0      elu(agg)+b1, [d(32)][c(256)]
    //   h2s  [32*72] @8192   h2 tile, padded stride
    __shared__ __align__(16) float big[10752];
    __shared__ float Zs[128];
    float*    es    = big;
    float*    ws    = big + 2048;
    unsigned* maskw = (unsigned*)(big + 6144);
    float*    ed    = big + 6656;
    float*    zp    = big + 6784;
    float*    tile  = big;
    float*    h2s   = big + 8192;

    const int b = blockIdx.x, d0 = blockIdx.y * 32;
    const int t = threadIdx.x, lane = t & 31, warp = t >> 5;
    const int h = t >> 6;   // head of this thread's column

    for (int i = t; i < NN * NH; i += 256) es[i] = g_E1s[b * NN * NH + i];
    if (t < 128) ed[t] = g_E1d[(b * NN + d0) * NH + t];

    const int* ap = adj + (size_t)b * NN * NN + d0;
    for (int s = warp; s < NN; s += 8) {
        int a = ap[s * NN + lane];
        unsigned mw = __ballot_sync(0xffffffffu, (a != 0) || (s == d0 + lane));
        if (lane == 0) maskw[s] = mw;
    }
    __syncthreads();

    u64 accp[16];
#pragma unroll
    for (int i = 0; i < 16; i++) accp[i] = pack2(0.f, 0.f);
    float zpart = 0.f;

    // fill-mapping: thread t -> fixed (head fhh, dst fdd), covers 16 sl values
    const int   fhh  = (t & 127) >> 5, fdd = t & 31;
    const float fedv = ed[fdd * NH + fhh];

    const float* H1b = g_H1 + ((size_t)(b * NN)) * HF + t;

    for (int s0 = 0; s0 < NN; s0 += 32) {
        // cooperative weight block: w = mask ? exp(leaky(e_dst+e_src)) : 0
#pragma unroll
        for (int i = 0; i < 16; i++) {
            int sl = (t >> 7) + 2 * i;
            int s  = s0 + sl;
            float sc = fedv + es[s * NH + fhh];
            sc = sc >= 0.f ? sc : 0.2f * sc;
            float wv = ((maskw[s] >> fdd) & 1u) ? __expf(sc) : 0.f;
            ws[(sl * NH + fhh) * 32 + fdd] = wv;
            zpart += wv;
        }
        __syncthreads();
        // aggregation: acc[d] += w[d,s,h] * H1[s,c]; 4-deep LDG prefetch
        for (int slq = 0; slq < 32; slq += 4) {
            float hv[4];
#pragma unroll
            for (int q = 0; q < 4; q++)
                hv[q] = H1b[(size_t)(s0 + slq + q) * HF];
#pragma unroll
            for (int q = 0; q < 4; q++) {
                u64 hh = pack2(hv[q], hv[q]);
                const ulonglong2* wp =
                    (const ulonglong2*)(ws + ((slq + q) * NH + h) * 32);
#pragma unroll
                for (int j = 0; j < 8; j++) {
                    ulonglong2 w2 = wp[j];
                    ffma2(accp[2 * j],     w2.x, hh);
                    ffma2(accp[2 * j + 1], w2.y, hh);
                }
            }
        }
        __syncthreads();
    }

    // reduce Z[d][h]; store reciprocal
    zp[t] = zpart;
    __syncthreads();
    if (t < 128) Zs[(t & 31) * NH + (t >> 5)] = 1.0f / (zp[t] + zp[t + 128]);
    __syncthreads();

    // normalize + b1 + ELU -> tile
    const float bv = b1[t];
#pragma unroll
    for (int p = 0; p < 16; p++) {
        float2 v = unpack2(accp[p]);
        int d = 2 * p;
        float o0 = v.x * Zs[d * NH + h] + bv;
        float o1 = v.y * Zs[(d + 1) * NH + h] + bv;
        tile[d * HF + t]       = o0 > 0.f ? o0 : expm1f(o0);
        tile[(d + 1) * HF + t] = o1 > 0.f ? o1 : expm1f(o1);
    }
    __syncthreads();

    // proj2: h2[d][o] = tile[d][:] @ W2[:, o]  (8 rows per thread, packed c)
    const int o = t & 63, grp = t >> 6;
    u64 accA[8], accB[8];
#pragma unroll
    for (int i = 0; i < 8; i++) { accA[i] = pack2(0.f, 0.f); accB[i] = pack2(0.f, 0.f); }
    for (int c = 0; c < HF; c += 4) {
        u64 wpA = pack2(W2[c * FOUT + o],       W2[(c + 1) * FOUT + o]);
        u64 wpB = pack2(W2[(c + 2) * FOUT + o], W2[(c + 3) * FOUT + o]);
#pragma unroll
        for (int i = 0; i < 8; i++) {
            ulonglong2 tv = *(const ulonglong2*)(tile + (grp * 8 + i) * HF + c);
            ffma2(accA[i], tv.x, wpA);
            ffma2(accB[i], tv.y, wpB);
        }
    }
#pragma unroll
    for (int i = 0; i < 8; i++) {
        float2 va = unpack2(accA[i]), vb = unpack2(accB[i]);
        float v = (va.x + va.y) + (vb.x + vb.y);
        int d = grp * 8 + i;
        g_H2[((size_t)(b * NN + d0 + d)) * FOUT + o] = v;
        h2s[d * H2S_STRIDE + o] = v;
    }
    __syncthreads();

    // e2_src/e2_dst for the tile: thread t<64 -> (node = t>>1, vec = t&1)
    if (t < 64) {
        const int node = t >> 1, vec = t & 1;
        const float* aw = vec ? a2d : a2s;
        const float4* hp = (const float4*)(h2s + node * H2S_STRIDE);
        float s = 0.f;
#pragma unroll
        for (int j = 0; j < 16; j++) {
            float4 hv = hp[j];
            s += hv.x * aw[4 * j] + hv.y * aw[4 * j + 1]
               + hv.z * aw[4 * j + 2] + hv.w * aw[4 * j + 3];
        }
        int idx = b * NN + d0 + node;
        if (vec == 0) g_E2s[idx] = s; else g_E2d[idx] = s;
    }
}

// ---------------------------------------------------------------------------
// Kernel C: layer-2 attention aggregation + b2 -> out. Grid (32, 16).
// Thread t owns o = t&63; dst rows grp*8 .. grp*8+7 (packed pairs).
// ---------------------------------------------------------------------------
__global__ void __launch_bounds__(256) kC(const int*   __restrict__ adj,
                                          const float* __restrict__ b2,
                                          float*       __restrict__ out) {
    __shared__ float es2[NN];
    __shared__ float ed2[32];
    __shared__ unsigned maskw[NN];
    __shared__ __align__(16) float ws2[64 * 32];
    __shared__ float zp[256];
    __shared__ float Z2[32];

    const int b = blockIdx.x, d0 = blockIdx.y * 32;
    const int t = threadIdx.x, lane = t & 31, warp = t >> 5;

    for (int i = t; i < NN; i += 256) es2[i] = g_E2s[b * NN + i];
    if (t < 32) ed2[t] = g_E2d[b * NN + d0 + t];

    const int* ap = adj + (size_t)b * NN * NN + d0;
    for (int s = warp; s < NN; s += 8) {
        int a = ap[s * NN + lane];
        unsigned mw = __ballot_sync(0xffffffffu, (a != 0) || (s == d0 + lane));
        if (lane == 0) maskw[s] = mw;
    }
    __syncthreads();

    u64 accp[4];
#pragma unroll
    for (int i = 0; i < 4; i++) accp[i] = pack2(0.f, 0.f);
    float zpart = 0.f;

    const int   fdd  = t & 31, fslb = t >> 5;
    const float fedv = ed2[fdd];
    const int   o = t & 63, grp = t >> 6;
    const float* H2b = g_H2 + (size_t)b * NN * FOUT + o;

    for (int s0 = 0; s0 < NN; s0 += 64) {
#pragma unroll
        for (int i = 0; i < 8; i++) {
            int sl = fslb + 8 * i;
            int s  = s0 + sl;
            float sc = fedv + es2[s];
            sc = sc >= 0.f ? sc : 0.2f * sc;
            float wv = ((maskw[s] >> fdd) & 1u) ? __expf(sc) : 0.f;
            ws2[sl * 32 + fdd] = wv;
            zpart += wv;
        }
        __syncthreads();
        for (int slq = 0; slq < 64; slq += 4) {
            float hv[4];
#pragma unroll
            for (int q = 0; q < 4; q++)
                hv[q] = H2b[(size_t)(s0 + slq + q) * FOUT];
#pragma unroll
            for (int q = 0; q < 4; q++) {
                u64 hh = pack2(hv[q], hv[q]);
                const ulonglong2* wp =
                    (const ulonglong2*)(ws2 + (slq + q) * 32 + grp * 8);
                ulonglong2 wa = wp[0], wb = wp[1];
                ffma2(accp[0], wa.x, hh);
                ffma2(accp[1], wa.y, hh);
                ffma2(accp[2], wb.x, hh);
                ffma2(accp[3], wb.y, hh);
            }
        }
        __syncthreads();
    }

    zp[t] = zpart;
    __syncthreads();
    if (t < 32) {
        float z = 0.f;
#pragma unroll
        for (int j = 0; j < 8; j++) z += zp[t + 32 * j];
        Z2[t] = 1.0f / z;
    }
    __syncthreads();

    const float bv = b2[o];
#pragma unroll
    for (int p = 0; p < 4; p++) {
        float2 v = unpack2(accp[p]);
        int d = grp * 8 + 2 * p;
        out[((size_t)(b * NN + d0 + d)) * FOUT + o]     = v.x * Z2[d] + bv;
        out[((size_t)(b * NN + d0 + d + 1)) * FOUT + o] = v.y * Z2[d + 1] + bv;
    }
}

// ---------------------------------------------------------------------------
extern "C" void kernel_launch(void* const* d_in, const int* in_sizes, int n_in,
                              void* d_out, int out_size) {
    const float* x   = (const float*)d_in[0];
    const int*   adj = (const int*)  d_in[1];
    const float* W1  = (const float*)d_in[2];
    const float* a1s = (const float*)d_in[3];
    const float* a1d = (const float*)d_in[4];
    const float* b1  = (const float*)d_in[5];
    const float* W2  = (const float*)d_in[6];
    const float* a2s = (const float*)d_in[7];
    const float* a2d = (const float*)d_in[8];
    const float* b2  = (const float*)d_in[9];
    float* out = (float*)d_out;

    kA<<<dim3(NB, 16), 256>>>(x, W1, a1s, a1d);
    kB<<<dim3(NB, 16), 256>>>(adj, b1, W2, a2s, a2d);
    kC<<<dim3(NB, 16), 256>>>(adj, b2, out);
}

// round 3
// speedup vs baseline: 1.9542x; 1.2983x over previous
#include <cuda_runtime.h>
#include <cuda_bf16.h>
#include <cstdint>

// Problem constants
#define NB   32
#define NN   512
#define FIN  64
#define NH   4
#define HID  64
#define HF   256   // NH*HID
#define FOUT 64

typedef unsigned long long u64;

// Scratch (static device arrays; no allocation)
__device__ float g_H1[NB * NN * HF];       // layer-1 projections h = x@W1   (16 MB)
__device__ float g_E1s[NB * NN * NH];
__device__ float g_E1d[NB * NN * NH];
__device__ float g_H2[NB * NN * FOUT];     // layer-2 projections (4 MB)
__device__ float g_E2s[NB * NN];
__device__ float g_E2d[NB * NN];

// ---- packed f32x2 helpers ----
__device__ __forceinline__ void ffma2(u64& d, u64 a, u64 b) {
    asm("fma.rn.f32x2 %0, %1, %2, %0;" : "+l"(d) : "l"(a), "l"(b));
}
__device__ __forceinline__ u64 pack2(float x, float y) {
    u64 r; asm("mov.b64 %0, {%1, %2};" : "=l"(r) : "f"(x), "f"(y)); return r;
}
__device__ __forceinline__ float2 unpack2(u64 v) {
    float2 r; asm("mov.b64 {%0, %1}, %2;" : "=f"(r.x), "=f"(r.y) : "l"(v)); return r;
}

// ---------------------------------------------------------------------------
// Kernel A: H1 = x @ W1 plus e1_src/e1_dst. Grid (32, 16): batch, 32-row tile.
// ---------------------------------------------------------------------------
#define HS_STRIDE 264   // padded row stride for hs (breaks bank conflicts)

__global__ void __launch_bounds__(256) kA(const float* __restrict__ x,
                                          const float* __restrict__ W1,
                                          const float* __restrict__ a1s,
                                          const float* __restrict__ a1d) {
    __shared__ __align__(16) float xs[32 * FIN];        // 8 KB
    __shared__ __align__(16) float hs[32 * HS_STRIDE];  // 33 KB
    __shared__ __align__(16) float av[2 * HF];          // a1s | a1d (2 KB)

    const int b = blockIdx.x, row0 = blockIdx.y * 32;
    const int t = threadIdx.x;

    const float* xp = x + ((size_t)(b * NN + row0)) * FIN;
    for (int i = t; i < 32 * FIN; i += 256) xs[i] = xp[i];
    {
        av[t]      = a1s[t];
        av[t + HF] = a1d[t];
    }

    // W1 column t, packed over k
    u64 w1p[32];
#pragma unroll
    for (int kk = 0; kk < 32; kk++)
        w1p[kk] = pack2(W1[(2 * kk) * HF + t], W1[(2 * kk + 1) * HF + t]);
    __syncthreads();

    float* H1p = g_H1 + ((size_t)(b * NN + row0)) * HF + t;
    for (int r = 0; r < 32; r++) {
        const ulonglong2* xr = (const ulonglong2*)(xs + r * FIN);
        u64 aA = pack2(0.f, 0.f), aB = pack2(0.f, 0.f);
#pragma unroll
        for (int q = 0; q < 16; q++) {
            ulonglong2 xv = xr[q];
            ffma2(aA, xv.x, w1p[2 * q]);
            ffma2(aB, xv.y, w1p[2 * q + 1]);
        }
        float2 fa = unpack2(aA), fb = unpack2(aB);
        float acc = (fa.x + fa.y) + (fb.x + fb.y);
        hs[r * HS_STRIDE + t] = acc;
        H1p[(size_t)r * HF] = acc;
    }
    __syncthreads();

    // Phase 2: thread t -> row = t>>3, h = (t>>1)&3, vec = t&1
    {
        const int row = t >> 3, h = (t >> 1) & 3, vec = t & 1;
        const float4* hp = (const float4*)(hs + row * HS_STRIDE + h * HID);
        const float4* ap = (const float4*)(av + vec * HF + h * HID);
        float s = 0.f;
#pragma unroll
        for (int j = 0; j < 16; j++) {
            float4 hv = hp[j], aw = ap[j];
            s += hv.x * aw.x + hv.y * aw.y + hv.z * aw.z + hv.w * aw.w;
        }
        int idx = (b * NN + row0 + row) * NH + h;
        if (vec == 0) g_E1s[idx] = s; else g_E1d[idx] = s;
    }
}

// ---------------------------------------------------------------------------
// Kernel B: layer-1 attention aggregation (fused unnormalized-sum + Z) with
// double-buffered weight blocks + depth-8 LDG pipelining, then +b1, ELU,
// proj2 (@W2), and e2_src/e2_dst. Grid (32, 16): batch, 32-dst tile.
// ---------------------------------------------------------------------------
#define H2S_STRIDE 72

__global__ void __launch_bounds__(256) kB(const int*   __restrict__ adj,
                                          const float* __restrict__ b1,
                                          const float* __restrict__ W2,
                                          const float* __restrict__ a2s,
                                          const float* __restrict__ a2d) {
    // Phase-1 layout inside big[11264] (44 KB):
    //   es   [2048]  @0       e1_src[s][h]
    //   ws   [8192]  @2048    DOUBLE-buffered weight blocks [2][sl(32)][h(4)][d(32)]
    //   maskw[512]u  @10240
    //   ed   [128]   @10752
    //   zp   [256]   @10880
    // Phase-2 overlays:
    //   tile [8192]  @0       elu(agg)+b1, [d(32)][c(256)]
    //   h2s  [32*72] @8192
    __shared__ __align__(16) float big[11264];
    __shared__ float Zs[128];
    float*    es    = big;
    float*    ws    = big + 2048;
    unsigned* maskw = (unsigned*)(big + 10240);
    float*    ed    = big + 10752;
    float*    zp    = big + 10880;
    float*    tile  = big;
    float*    h2s   = big + 8192;

    const int b = blockIdx.x, d0 = blockIdx.y * 32;
    const int t = threadIdx.x, lane = t & 31, warp = t >> 5;
    const int h = t >> 6;   // head of this thread's column

    for (int i = t; i < NN * NH; i += 256) es[i] = g_E1s[b * NN * NH + i];
    if (t < 128) ed[t] = g_E1d[(b * NN + d0) * NH + t];

    const int* ap = adj + (size_t)b * NN * NN + d0;
    for (int s = warp; s < NN; s += 8) {
        int a = ap[s * NN + lane];
        unsigned mw = __ballot_sync(0xffffffffu, (a != 0) || (s == d0 + lane));
        if (lane == 0) maskw[s] = mw;
    }
    __syncthreads();

    u64 accp[16];
#pragma unroll
    for (int i = 0; i < 16; i++) accp[i] = pack2(0.f, 0.f);
    float zpart = 0.f;

    // fill-mapping: thread t -> fixed (head fhh, dst fdd), covers 16 sl values
    const int   fhh  = (t & 127) >> 5, fdd = t & 31;
    const float fedv = ed[fdd * NH + fhh];
    const int   slb  = t >> 7;      // 0 or 1: which parity of sl this thread fills

    const float* H1b = g_H1 + ((size_t)(b * NN)) * HF + t;

    // fill weight block blk into buffer blk&1
#define FILL_WS(blk)                                                          \
    {                                                                         \
        float* wb = ws + (((blk) & 1) << 12);                                 \
        _Pragma("unroll")                                                     \
        for (int i = 0; i < 16; i++) {                                        \
            int sl = slb + 2 * i;                                             \
            int s  = (blk) * 32 + sl;                                         \
            float sc = fedv + es[s * NH + fhh];                               \
            sc = sc >= 0.f ? sc : 0.2f * sc;                                  \
            float wv = ((maskw[s] >> fdd) & 1u) ? __expf(sc) : 0.f;           \
            wb[(sl * NH + fhh) * 32 + fdd] = wv;                              \
            zpart += wv;                                                      \
        }                                                                     \
    }

    FILL_WS(0);
    __syncthreads();

    float hv[8];
#pragma unroll
    for (int q = 0; q < 8; q++) hv[q] = H1b[(size_t)q * HF];

    for (int blk = 0; blk < 16; blk++) {
        // fill next block's weights first (other buffer) — overlaps MUFU with FFMA2
        if (blk < 15) FILL_WS(blk + 1);

        const float* wbase = ws + ((blk & 1) << 12);
#pragma unroll
        for (int sub = 0; sub < 4; sub++) {
            // prefetch the NEXT 8 rows while computing the current 8
            float hn[8];
            int nbase = blk * 32 + sub * 8 + 8;
            if (nbase < NN) {
#pragma unroll
                for (int q = 0; q < 8; q++)
                    hn[q] = H1b[(size_t)(nbase + q) * HF];
            }
#pragma unroll
            for (int q = 0; q < 8; q++) {
                u64 hh = pack2(hv[q], hv[q]);
                const ulonglong2* wp =
                    (const ulonglong2*)(wbase + ((sub * 8 + q) * NH + h) * 32);
#pragma unroll
                for (int j = 0; j < 8; j++) {
                    ulonglong2 w2 = wp[j];
                    ffma2(accp[2 * j],     w2.x, hh);
                    ffma2(accp[2 * j + 1], w2.y, hh);
                }
            }
#pragma unroll
            for (int q = 0; q < 8; q++) hv[q] = hn[q];
        }
        __syncthreads();
    }

    // reduce Z[d][h]; store reciprocal
    zp[t] = zpart;
    __syncthreads();
    if (t < 128) Zs[(t & 31) * NH + (t >> 5)] = 1.0f / (zp[t] + zp[t + 128]);
    __syncthreads();

    // normalize + b1 + ELU -> tile
    const float bv = b1[t];
#pragma unroll
    for (int p = 0; p < 16; p++) {
        float2 v = unpack2(accp[p]);
        int d = 2 * p;
        float o0 = v.x * Zs[d * NH + h] + bv;
        float o1 = v.y * Zs[(d + 1) * NH + h] + bv;
        tile[d * HF + t]       = o0 > 0.f ? o0 : expm1f(o0);
        tile[(d + 1) * HF + t] = o1 > 0.f ? o1 : expm1f(o1);
    }
    __syncthreads();

    // proj2: h2[d][o] = tile[d][:] @ W2[:, o]  (8 rows per thread, packed c)
    const int o = t & 63, grp = t >> 6;
    u64 accA[8], accB[8];
#pragma unroll
    for (int i = 0; i < 8; i++) { accA[i] = pack2(0.f, 0.f); accB[i] = pack2(0.f, 0.f); }
    for (int c = 0; c < HF; c += 4) {
        u64 wpA = pack2(W2[c * FOUT + o],       W2[(c + 1) * FOUT + o]);
        u64 wpB = pack2(W2[(c + 2) * FOUT + o], W2[(c + 3) * FOUT + o]);
#pragma unroll
        for (int i = 0; i < 8; i++) {
            ulonglong2 tv = *(const ulonglong2*)(tile + (grp * 8 + i) * HF + c);
            ffma2(accA[i], tv.x, wpA);
            ffma2(accB[i], tv.y, wpB);
        }
    }
#pragma unroll
    for (int i = 0; i < 8; i++) {
        float2 va = unpack2(accA[i]), vb = unpack2(accB[i]);
        float v = (va.x + va.y) + (vb.x + vb.y);
        int d = grp * 8 + i;
        g_H2[((size_t)(b * NN + d0 + d)) * FOUT + o] = v;
        h2s[d * H2S_STRIDE + o] = v;
    }
    __syncthreads();

    // e2_src/e2_dst for the tile: thread t<64 -> (node = t>>1, vec = t&1)
    if (t < 64) {
        const int node = t >> 1, vec = t & 1;
        const float* aw = vec ? a2d : a2s;
        const float4* hp = (const float4*)(h2s + node * H2S_STRIDE);
        float s = 0.f;
#pragma unroll
        for (int j = 0; j < 16; j++) {
            float4 hvv = hp[j];
            s += hvv.x * aw[4 * j] + hvv.y * aw[4 * j + 1]
               + hvv.z * aw[4 * j + 2] + hvv.w * aw[4 * j + 3];
        }
        int idx = b * NN + d0 + node;
        if (vec == 0) g_E2s[idx] = s; else g_E2d[idx] = s;
    }
#undef FILL_WS
}

// ---------------------------------------------------------------------------
// Kernel C: layer-2 attention aggregation + b2 -> out. Grid (32, 16).
// Double-buffered weights + depth-8 LDG pipelining.
// ---------------------------------------------------------------------------
__global__ void __launch_bounds__(256) kC(const int*   __restrict__ adj,
                                          const float* __restrict__ b2,
                                          float*       __restrict__ out) {
    __shared__ float es2[NN];
    __shared__ float ed2[32];
    __shared__ unsigned maskw[NN];
    __shared__ __align__(16) float ws2[2 * 64 * 32];   // double buffer, 16 KB
    __shared__ float zp[256];
    __shared__ float Z2[32];

    const int b = blockIdx.x, d0 = blockIdx.y * 32;
    const int t = threadIdx.x, lane = t & 31, warp = t >> 5;

    for (int i = t; i < NN; i += 256) es2[i] = g_E2s[b * NN + i];
    if (t < 32) ed2[t] = g_E2d[b * NN + d0 + t];

    const int* ap = adj + (size_t)b * NN * NN + d0;
    for (int s = warp; s < NN; s += 8) {
        int a = ap[s * NN + lane];
        unsigned mw = __ballot_sync(0xffffffffu, (a != 0) || (s == d0 + lane));
        if (lane == 0) maskw[s] = mw;
    }
    __syncthreads();

    u64 accp[4];
#pragma unroll
    for (int i = 0; i < 4; i++) accp[i] = pack2(0.f, 0.f);
    float zpart = 0.f;

    const int   fdd  = t & 31, fslb = t >> 5;
    const float fedv = ed2[fdd];
    const int   o = t & 63, grp = t >> 6;
    const float* H2b = g_H2 + (size_t)b * NN * FOUT + o;

#define FILL_WS2(blk)                                                         \
    {                                                                         \
        float* wb = ws2 + (((blk) & 1) << 11);                                \
        _Pragma("unroll")                                                     \
        for (int i = 0; i < 8; i++) {                                         \
            int sl = fslb + 8 * i;                                            \
            int s  = (blk) * 64 + sl;                                         \
            float sc = fedv + es2[s];                                         \
            sc = sc >= 0.f ? sc : 0.2f * sc;                                  \
            float wv = ((maskw[s] >> fdd) & 1u) ? __expf(sc) : 0.f;           \
            wb[sl * 32 + fdd] = wv;                                           \
            zpart += wv;                                                      \
        }                                                                     \
    }

    FILL_WS2(0);
    __syncthreads();

    float hv[8];
#pragma unroll
    for (int q = 0; q < 8; q++) hv[q] = H2b[(size_t)q * FOUT];

    for (int blk = 0; blk < 8; blk++) {
        if (blk < 7) FILL_WS2(blk + 1);

        const float* wbase = ws2 + ((blk & 1) << 11);
#pragma unroll
        for (int sub = 0; sub < 8; sub++) {
            float hn[8];
            int nbase = blk * 64 + sub * 8 + 8;
            if (nbase < NN) {
#pragma unroll
                for (int q = 0; q < 8; q++)
                    hn[q] = H2b[(size_t)(nbase + q) * FOUT];
            }
#pragma unroll
            for (int q = 0; q < 8; q++) {
                u64 hh = pack2(hv[q], hv[q]);
                const ulonglong2* wp =
                    (const ulonglong2*)(wbase + (sub * 8 + q) * 32 + grp * 8);
                ulonglong2 wa = wp[0], wb2 = wp[1];
                ffma2(accp[0], wa.x, hh);
                ffma2(accp[1], wa.y, hh);
                ffma2(accp[2], wb2.x, hh);
                ffma2(accp[3], wb2.y, hh);
            }
#pragma unroll
            for (int q = 0; q < 8; q++) hv[q] = hn[q];
        }
        __syncthreads();
    }

    zp[t] = zpart;
    __syncthreads();
    if (t < 32) {
        float z = 0.f;
#pragma unroll
        for (int j = 0; j < 8; j++) z += zp[t + 32 * j];
        Z2[t] = 1.0f / z;
    }
    __syncthreads();

    const float bv = b2[o];
#pragma unroll
    for (int p = 0; p < 4; p++) {
        float2 v = unpack2(accp[p]);
        int d = grp * 8 + 2 * p;
        out[((size_t)(b * NN + d0 + d)) * FOUT + o]     = v.x * Z2[d] + bv;
        out[((size_t)(b * NN + d0 + d + 1)) * FOUT + o] = v.y * Z2[d + 1] + bv;
    }
#undef FILL_WS2
}

// ---------------------------------------------------------------------------
extern "C" void kernel_launch(void* const* d_in, const int* in_sizes, int n_in,
                              void* d_out, int out_size) {
    const float* x   = (const float*)d_in[0];
    const int*   adj = (const int*)  d_in[1];
    const float* W1  = (const float*)d_in[2];
    const float* a1s = (const float*)d_in[3];
    const float* a1d = (const float*)d_in[4];
    const float* b1  = (const float*)d_in[5];
    const float* W2  = (const float*)d_in[6];
    const float* a2s = (const float*)d_in[7];
    const float* a2d = (const float*)d_in[8];
    const float* b2  = (const float*)d_in[9];
    float* out = (float*)d_out;

    kA<<<dim3(NB, 16), 256>>>(x, W1, a1s, a1d);
    kB<<<dim3(NB, 16), 256>>>(adj, b1, W2, a2s, a2d);
    kC<<<dim3(NB, 16), 256>>>(adj, b2, out);
}